// round 17
// baseline (speedup 1.0000x reference)
#include <cuda_runtime.h>
#include <cstdint>
#include <cfloat>

#define B_     256
#define C_     2048
#define K_     18        // landmarks (GEMM N)
#define HW_    192       // GEMM K
#define TPB    256
#define ROWS   256       // c-rows per item; warp owns 32 rows = 2 chunks
#define NPAD   24
#define NT     3
#define STRIDE 196       // row stride (words) for BOTH A chunks and B: 196%32=4 -> conflict-free
#define CH_ROWS 16       // chunk = 16 rows x full K (12KB contiguous in GMEM)
#define CH_WORDS (CH_ROWS*STRIDE)   // 3136
#define NKC    (HW_/8)   // 24 K-chunks per chunk

#define NTILE  (C_/ROWS)            // 8 m-tiles per b
#define NITEMS (B_*NTILE)           // 2048 work items
#define GRID   152                  // 1 CTA per SM

#define SM_B_WORDS (NPAD*STRIDE)             // 4704
#define SM_A_WORDS (8*2*CH_WORDS)            // 8 warps x 2 buffers
#define SMEM_TOTAL ((SM_B_WORDS + SM_A_WORDS + 4)*4)   // 219,536 B

__device__ unsigned int g_item;

__device__ __forceinline__ uint32_t s2u(const void* p) {
    uint32_t a;
    asm("{ .reg .u64 t; cvta.to.shared.u64 t, %1; cvt.u32.u64 %0, t; }" : "=r"(a) : "l"(p));
    return a;
}
__device__ __forceinline__ void cpasync16(uint32_t s, const void* g) {
    asm volatile("cp.async.cg.shared.global.L2::256B [%0], [%1], 16;" :: "r"(s), "l"(g));
}
__device__ __forceinline__ void cp_commit() { asm volatile("cp.async.commit_group;" ::: "memory"); }
template <int N> __device__ __forceinline__ void cp_wait() {
    asm volatile("cp.async.wait_group %0;" :: "n"(N) : "memory");
}
__device__ __forceinline__ uint32_t f2tf32(float f) {
    uint32_t r;
    asm("cvt.rna.tf32.f32 %0, %1;" : "=r"(r) : "f"(f));
    return r;
}
__device__ __forceinline__ void mma_tf32(float& d0, float& d1, float& d2, float& d3,
                                         uint32_t a0, uint32_t a1, uint32_t a2, uint32_t a3,
                                         uint32_t b0, uint32_t b1) {
    asm volatile("mma.sync.aligned.m16n8k8.row.col.f32.tf32.tf32.f32 "
                 "{%0,%1,%2,%3}, {%4,%5,%6,%7}, {%8,%9}, {%0,%1,%2,%3};"
                 : "+f"(d0), "+f"(d1), "+f"(d2), "+f"(d3)
                 : "r"(a0), "r"(a1), "r"(a2), "r"(a3), "r"(b0), "r"(b1));
}
__device__ __forceinline__ float shfl_xor_max(float v, int m) {
    float r;
    asm volatile("shfl.sync.bfly.b32 %0, %1, %2, 0x1F, 0xFFFFFFFF;" : "=f"(r) : "f"(v), "r"(m));
    return fmaxf(v, r);
}

extern __shared__ float smem[];

__global__ void pgfa_init_kernel() { g_item = GRID; }

__global__ __launch_bounds__(TPB)
void pgfa_mma_kernel(const float* __restrict__ feat,
                     const float* __restrict__ masks,
                     const float* __restrict__ pgf,
                     float* __restrict__ out)
{
    uint32_t* s_b    = reinterpret_cast<uint32_t*>(smem);          // [NPAD][STRIDE] tf32 bits
    float*    s_a    = smem + SM_B_WORDS;                          // 8 warps x 2 x CH_WORDS
    int*      s_next = reinterpret_cast<int*>(smem + SM_B_WORDS + SM_A_WORDS);

    const int tid  = threadIdx.x;
    const int wid  = tid >> 5;
    const int lane = tid & 31;
    const int gid  = lane >> 2;
    const int tig  = lane & 3;
    const uint32_t sabase = s2u(s_a);
    float* const wbuf = s_a + wid * 2 * CH_WORDS;

    auto stage_B = [&](int b) {
        const float* msrc = masks + (size_t)b * K_ * HW_;
        for (int i = tid; i < K_ * HW_; i += TPB) {
            int n = i / HW_, k = i - n * HW_;
            s_b[n * STRIDE + k] = f2tf32(msrc[i]);
        }
        for (int i = tid; i < (NPAD - K_) * HW_; i += TPB) {
            int n = K_ + i / HW_, k = i % HW_;
            s_b[n * STRIDE + k] = 0u;
        }
    };

    // One chunk = this warp's 16 consecutive rows x full K = 12KB CONTIGUOUS gmem,
    // issued in strict address order (one same-page DRAM burst per row region).
    auto issue_chunk = [&](const float* fb, int ch, int buf) {
        const float* g0 = fb + (size_t)(wid * 32 + ch * CH_ROWS) * HW_;
        uint32_t sb = sabase + (uint32_t)(wid * 2 * CH_WORDS + buf * CH_WORDS) * 4;
        #pragma unroll
        for (int j = 0; j < 24; j++) {              // 768 float4 / 32 lanes
            int f   = j * 32 + lane;                // ascending address order
            int row = f / 48;                       // 48 float4 per 768B row
            int c4  = f % 48;
            cpasync16(sb + (uint32_t)(row * STRIDE + c4 * 4) * 4, g0 + (size_t)f * 4);
        }
        cp_commit();
    };

    const float inv = 1.0f / (float)HW_;

    // Compute ALL of K for one 16-row m-tile, then epilogue those rows.
    auto compute_chunk = [&](int buf, int grow, size_t orow) {
        const float* cb = wbuf + buf * CH_WORDS;
        float d[NT][4];
        #pragma unroll
        for (int nt = 0; nt < NT; nt++)
            #pragma unroll
            for (int j = 0; j < 4; j++) d[nt][j] = 0.0f;

        #pragma unroll 4
        for (int kc = 0; kc < NKC; kc++) {
            const int kg = kc * 8;
            uint32_t bf[NT][2];
            #pragma unroll
            for (int nt = 0; nt < NT; nt++) {
                int n = nt * 8 + gid;
                bf[nt][0] = s_b[n * STRIDE + kg + tig];
                bf[nt][1] = s_b[n * STRIDE + kg + tig + 4];
            }
            uint32_t a0 = __float_as_uint(cb[gid       * STRIDE + kg + tig]);
            uint32_t a1 = __float_as_uint(cb[(gid + 8) * STRIDE + kg + tig]);
            uint32_t a2 = __float_as_uint(cb[gid       * STRIDE + kg + tig + 4]);
            uint32_t a3 = __float_as_uint(cb[(gid + 8) * STRIDE + kg + tig + 4]);
            #pragma unroll
            for (int nt = 0; nt < NT; nt++)
                mma_tf32(d[nt][0], d[nt][1], d[nt][2], d[nt][3],
                         a0, a1, a2, a3, bf[nt][0], bf[nt][1]);
        }

        float m0 = -FLT_MAX, m1 = -FLT_MAX;
        #pragma unroll
        for (int nt = 0; nt < NT; nt++)
            #pragma unroll
            for (int j = 0; j < 2; j++) {
                int n = nt * 8 + tig * 2 + j;
                if (n < K_) {
                    m0 = fmaxf(m0, d[nt][j]);
                    m1 = fmaxf(m1, d[nt][2 + j]);
                }
            }
        m0 = shfl_xor_max(m0, 1); m0 = shfl_xor_max(m0, 2);
        m1 = shfl_xor_max(m1, 1); m1 = shfl_xor_max(m1, 2);
        if (tig == 0) {
            out[orow + C_ + grow + gid]     = m0 * inv;
            out[orow + C_ + grow + gid + 8] = m1 * inv;
        }
    };

    int item = blockIdx.x;
    stage_B(item >> 3);
    const float* fbase = feat + ((size_t)(item >> 3) * C_ + (item & (NTILE - 1)) * ROWS) * HW_;
    issue_chunk(fbase, 0, 0);
    __syncthreads();                      // s_b visible

    while (true) {
        issue_chunk(fbase, 1, 1);
        if (tid == 0) *s_next = (int)atomicAdd(&g_item, 1u);   // claim-ahead by 1

        const int b       = item >> 3;
        const int rowbase = (item & (NTILE - 1)) * ROWS;
        const size_t orow = (size_t)b * (2 * C_);
        out[orow + rowbase + tid] = pgf[(size_t)b * C_ + rowbase + tid];

        __syncthreads();                  // publish s_next
        const int nxt = *s_next;
        const bool hv = (nxt < NITEMS);
        const float* nfbase = hv
            ? feat + ((size_t)(nxt >> 3) * C_ + (nxt & (NTILE - 1)) * ROWS) * HW_
            : fbase;

        cp_wait<1>(); __syncwarp();
        compute_chunk(0, rowbase + wid * 32, orow);

        if (hv) { issue_chunk(nfbase, 0, 0); cp_wait<1>(); }   // next item's chunk0 in flight
        else    { cp_wait<0>(); }
        __syncwarp();
        compute_chunk(1, rowbase + wid * 32 + CH_ROWS, orow);

        if (!hv) break;

        __syncthreads();                  // all warps done reading s_b
        stage_B(nxt >> 3);
        __syncthreads();                  // publish s_b
        item  = nxt;
        fbase = nfbase;
    }
}

extern "C" void kernel_launch(void* const* d_in, const int* in_sizes, int n_in,
                              void* d_out, int out_size)
{
    const float* feat  = (const float*)d_in[0];
    const float* masks = (const float*)d_in[1];
    const float* pgf   = (const float*)d_in[2];
    float*       out   = (float*)d_out;

    cudaFuncSetAttribute(pgfa_mma_kernel,
                         cudaFuncAttributeMaxDynamicSharedMemorySize, SMEM_TOTAL);

    pgfa_init_kernel<<<1, 1>>>();
    pgfa_mma_kernel<<<GRID, TPB, SMEM_TOTAL>>>(feat, masks, pgf, out);
}